// round 15
// baseline (speedup 1.0000x reference)
#include <cuda_runtime.h>
#include <cuda_bf16.h>
#include <cstdint>

#define BB   8
#define NCAM 6
#define DD   41
#define FHH  8
#define FWW  22
#define CC   64
#define NXY  200
#define PTS_PER_CAM (DD*FHH*FWW)          /* 7216 */
#define NPTS (BB*NCAM*PTS_PER_CAM)        /* 346368 */
#define GRID_CELLS (BB*NXY*NXY)           /* 320000 */
#define NCAMS (BB*NCAM)                   /* 48 */
#define SCAT_BLOCKS (NPTS*2/256)          /* 2706: 2 lanes per point */
#define FILL_BLOCKS 1250                  /* 1250*4096 float4 = whole out */

// Scratch: channel-last voxel grid [B,200,200,C]  (81.92 MB, static device alloc)
// INVARIANT: all-zero at the start of every kernel_launch call. Static init
// zeroes it; transpose_out re-zeroes every touched cell after reading it.
__device__ float g_scratch[(size_t)GRID_CELLS * CC];
// Per-cell touched flag. INVARIANT: all-zero at call start; scatter sets,
// transpose_out reads + clears.
__device__ unsigned g_count[GRID_CELLS];
// Per-camera fused params: inv(post_rots)[9], post_trans[3], combine[9], trans[3]
__device__ float g_cam[NCAMS][24];

// ---------------------------------------------------------------------------
// Reciprocal without div.rn.f64: f32 estimate + 2 double Newton steps
// (< 1 double ulp — invisible after the final cast to f32).
__device__ __forceinline__ double rcp_newton(double d) {
    double r = (double)__frcp_rn((float)d);
    double e = fma(-d, r, 1.0);  r = fma(r, e, r);
    e        = fma(-d, r, 1.0);  r = fma(r, e, r);
    return r;
}

// ---------------------------------------------------------------------------
// Camera setup: 96 threads, one 3x3 inverse each, no f64 divides.
// PDL trigger at ENTRY: dependent blocks may launch immediately (fill blocks
// need no params; scatter blocks GridDependencySync before touching g_cam).
__global__ void cam_setup(const float* __restrict__ rots,
                          const float* __restrict__ trans,
                          const float* __restrict__ intrins,
                          const float* __restrict__ post_rots,
                          const float* __restrict__ post_trans) {
    cudaTriggerProgrammaticLaunchCompletion();
    __shared__ double sik[NCAMS][9];     // inv(intrins)
    int t = threadIdx.x;                 // 0..95
    int role = t / NCAMS;                // 0: post_rots, 1: intrins
    int cam  = t - role * NCAMS;

    if (t < 2 * NCAMS) {
        const float* src = (role == 0 ? post_rots : intrins) + cam * 9;
        double a[9];
        #pragma unroll
        for (int k = 0; k < 9; k++) a[k] = src[k];
        double det = a[0]*(a[4]*a[8] - a[5]*a[7])
                   + a[1]*(a[5]*a[6] - a[3]*a[8])
                   + a[2]*(a[3]*a[7] - a[4]*a[6]);
        double id = rcp_newton(det);
        #pragma unroll
        for (int r = 0; r < 3; r++) {
            #pragma unroll
            for (int c = 0; c < 3; c++) {
                int c1 = (c + 1) % 3, c2 = (c + 2) % 3;
                int r1 = (r + 1) % 3, r2 = (r + 2) % 3;
                double adj = a[c1*3 + r1] * a[c2*3 + r2]
                           - a[c1*3 + r2] * a[c2*3 + r1];
                double v = adj * id;
                if (role == 0) g_cam[cam][r*3 + c] = (float)v;
                else           sik[cam][r*3 + c]   = v;
            }
        }
        if (role == 0) {
            #pragma unroll
            for (int j = 0; j < 3; j++) {
                g_cam[cam][9 + j]  = post_trans[cam*3 + j];
                g_cam[cam][21 + j] = trans[cam*3 + j];
            }
        }
    }
    __syncthreads();
    if (t < NCAMS) {
        const float* rt = rots + t * 9;
        #pragma unroll
        for (int r = 0; r < 3; r++) {
            #pragma unroll
            for (int c = 0; c < 3; c++) {
                double s = (double)rt[r*3+0] * sik[t][0*3 + c]
                         + (double)rt[r*3+1] * sik[t][1*3 + c]
                         + (double)rt[r*3+2] * sik[t][2*3 + c];
                g_cam[t][12 + r*3 + c] = (float)s;
            }
        }
    }
}

// ---------------------------------------------------------------------------
// Fused output-zero-fill + voxelize + scatter-add.
// Blocks [0, FILL_BLOCKS) zero d_out (no camera dependency, no grid sync):
// they stream concurrently with cam_setup and the atomic phase.
// Remaining blocks: TWO lanes per point (each kept thread: 8 float4 loads +
// 8 vector REDs, issued in two batches of 4 to bound live registers).
// Features are loaded ONLY for points that survive the cull (~20%).
__global__ void scatter(const float* __restrict__ x_feats,
                        float* __restrict__ out) {
    int tid = threadIdx.x;               // 256 threads
    int bid = blockIdx.x;

    if (bid < FILL_BLOCKS) {
        float4* o4 = reinterpret_cast<float4*>(out);
        float4 z4 = make_float4(0.f, 0.f, 0.f, 0.f);
        int base = bid * 4096 + tid;
        #pragma unroll
        for (int i = 0; i < 16; i++)
            __stcs(o4 + base + i * 256, z4);
        return;
    }

    cudaGridDependencySynchronize();    // wait for cam_setup's writes

    int gid = (bid - FILL_BLOCKS) * 256 + tid;   // exact grid, no guard
    int point = gid >> 1;
    int c2    = gid & 1;                 // which half of the 64 channels

    int cam = point / PTS_PER_CAM;
    int r   = point - cam * PTS_PER_CAM;
    int d   = r / (FHH * FWW);
    int r2  = r - d * (FHH * FWW);
    int h   = r2 / FWW;
    int w   = r2 - h * FWW;

    const float* cp = g_cam[cam];
    const float XSTEP = 351.0f / 21.0f;   // matches f32 linspace step
    const float YSTEP = 127.0f / 7.0f;
    float fx = (float)w * XSTEP;
    float fy = (float)h * YSTEP;
    float fz = 4.0f + (float)d;

    float px = fx - cp[9];
    float py = fy - cp[10];
    float pz = fz - cp[11];
    // q = inv(post_rots) @ p   (fma chain, k-order accumulation)
    float q0 = fmaf(cp[2], pz, fmaf(cp[1], py, cp[0]*px));
    float q1 = fmaf(cp[5], pz, fmaf(cp[4], py, cp[3]*px));
    float q2 = fmaf(cp[8], pz, fmaf(cp[7], py, cp[6]*px));
    // unproject: (u*d, v*d, d)
    float r0 = q0 * q2;
    float r1 = q1 * q2;
    float r2v = q2;
    // geom = combine @ r + trans
    float g0 = fmaf(cp[14], r2v, fmaf(cp[13], r1, cp[12]*r0)) + cp[21];
    float g1 = fmaf(cp[17], r2v, fmaf(cp[16], r1, cp[15]*r0)) + cp[22];
    float g2 = fmaf(cp[20], r2v, fmaf(cp[19], r1, cp[18]*r0)) + cp[23];

    // quantize: (geom - (BX - DX/2)) / DX, truncate toward zero
    float v0 = (g0 + 50.0f) / 0.5f;
    float v1 = (g1 + 50.0f) / 0.5f;
    float v2 = (g2 + 10.0f) / 20.0f;
    int i0 = (int)v0;
    int i1 = (int)v1;
    int i2 = (int)v2;

    if (i0 < 0 || i0 >= NXY || i1 < 0 || i1 >= NXY || i2 != 0) return;
    int b   = cam / NCAM;
    int vox = (b * NXY + i0) * NXY + i1;

    if (c2 == 0) g_count[vox] = 1u;   // benign race: all writers store 1

    // Features loaded only for kept points: 8 float4s in two batches of 4.
    const float4* xf = reinterpret_cast<const float4*>(x_feats) + point * 16 + c2 * 8;
    float* dst = g_scratch + (unsigned)vox * CC + c2 * 32;
    #pragma unroll
    for (int batch = 0; batch < 2; batch++) {
        float4 f0 = __ldcs(xf + batch * 4 + 0);
        float4 f1 = __ldcs(xf + batch * 4 + 1);
        float4 f2 = __ldcs(xf + batch * 4 + 2);
        float4 f3 = __ldcs(xf + batch * 4 + 3);
        float* p = dst + batch * 16;
        asm volatile("red.global.add.v4.f32 [%0], {%1,%2,%3,%4};"
                     :: "l"(p), "f"(f0.x), "f"(f0.y), "f"(f0.z), "f"(f0.w) : "memory");
        asm volatile("red.global.add.v4.f32 [%0], {%1,%2,%3,%4};"
                     :: "l"(p + 4), "f"(f1.x), "f"(f1.y), "f"(f1.z), "f"(f1.w) : "memory");
        asm volatile("red.global.add.v4.f32 [%0], {%1,%2,%3,%4};"
                     :: "l"(p + 8), "f"(f2.x), "f"(f2.y), "f"(f2.z), "f"(f2.w) : "memory");
        asm volatile("red.global.add.v4.f32 [%0], {%1,%2,%3,%4};"
                     :: "l"(p + 12), "f"(f3.x), "f"(f3.y), "f"(f3.z), "f"(f3.w) : "memory");
    }
}

// ---------------------------------------------------------------------------
// Transpose [B,200(x),200(y),C] -> out [B,C,200(x),200(y)] — TOUCHED TILES
// ONLY. Untouched tiles were already zero-filled by scatter's fill blocks:
// skip read AND write. Touched cells are read once and zeroed behind the
// read (maintains the all-zero scratch invariant). g_count always cleared.
__global__ void transpose_out(float* __restrict__ out) {
    __shared__ float tile[2][32][65];
    __shared__ unsigned s_touch[2];
    int tid = threadIdx.x;               // 256 threads
    int xg  = blockIdx.y;                // 0..799 -> 2 consecutive bx
    int y0  = blockIdx.x * 32;
    int bx0 = xg * 2;
    int b   = bx0 / NXY;                 // 200 % 2 == 0: never crosses b
    int x0  = bx0 - b * NXY;

    cudaGridDependencySynchronize();    // wait for scatter's atomics/flags

    if (tid < 64) {
        int u  = tid >> 5;
        int yl = tid & 31;
        int y  = y0 + yl;
        unsigned fl = 0u;
        if (y < NXY) {
            int cell = (bx0 + u) * NXY + y;
            fl = g_count[cell];
            if (fl) g_count[cell] = 0u;
        }
        unsigned m = __ballot_sync(0xffffffffu, fl != 0u);
        if (yl == 0) s_touch[u] = m;
    }
    __syncthreads();

    if ((s_touch[0] | s_touch[1]) == 0u) return;   // fill already wrote zeros

    // Load phase: thread covers (c4, ylo) and (c4, ylo+16) for both rows.
    int c4  = tid & 15;
    int ylo = tid >> 4;                  // 0..15
    float4* sc4 = reinterpret_cast<float4*>(g_scratch);
    float4 z4 = make_float4(0.f, 0.f, 0.f, 0.f);
    #pragma unroll
    for (int u = 0; u < 2; u++) {
        unsigned m = s_touch[u];
        if (!m) continue;                // tile[u] stale; store phase skips it
        #pragma unroll
        for (int i = 0; i < 2; i++) {
            int yl = ylo + 16 * i;
            int yg = y0 + yl;
            bool live = (yg < NXY) && ((m >> yl) & 1u);
            float4 v = z4;
            unsigned idx = (unsigned)((bx0 + u) * NXY + yg) * 16 + c4;
            if (live) {
                v = __ldcs(sc4 + idx);
                __stcs(sc4 + idx, z4);
            }
            if (yg < NXY) {
                tile[u][yl][c4 * 4 + 0] = v.x;
                tile[u][yl][c4 * 4 + 1] = v.y;
                tile[u][yl][c4 * 4 + 2] = v.z;
                tile[u][yl][c4 * 4 + 3] = v.w;
            }
        }
    }
    __syncthreads();

    // Store phase: float4 along y, fully coalesced; conflict-free smem reads.
    int lane = tid & 31;
    int warp = tid >> 5;                 // 0..7
    int cgrp = lane >> 3;                // 0..3
    int yseg = lane & 7;                 // 0..7
    int yg4  = y0 + yseg * 4;
    float4* out4 = reinterpret_cast<float4*>(out);

    if (yg4 < NXY) {
        #pragma unroll
        for (int u = 0; u < 2; u++) {
            if (!s_touch[u]) continue;   // zeros already present from fill
            int x = x0 + u;
            #pragma unroll
            for (int j = 0; j < 2; j++) {
                int c = warp * 4 + cgrp + j * 32;
                int yl = yseg * 4;
                float4 v;
                v.x = tile[u][yl + 0][c];
                v.y = tile[u][yl + 1][c];
                v.z = tile[u][yl + 2][c];
                v.w = tile[u][yl + 3][c];
                unsigned o4 = ((((unsigned)b * CC + c) * NXY + x) * NXY + yg4) >> 2;
                __stcs(out4 + o4, v);
            }
        }
    }
}

// ---------------------------------------------------------------------------
extern "C" void kernel_launch(void* const* d_in, const int* in_sizes, int n_in,
                              void* d_out, int out_size) {
    const float* x_feats    = (const float*)d_in[0];
    const float* rots       = (const float*)d_in[1];
    const float* trans      = (const float*)d_in[2];
    const float* intrins    = (const float*)d_in[3];
    const float* post_rots  = (const float*)d_in[4];
    const float* post_trans = (const float*)d_in[5];
    float* out = (float*)d_out;

    cam_setup<<<1, 96>>>(rots, trans, intrins, post_rots, post_trans);

    cudaLaunchAttribute attrs[1];
    attrs[0].id = cudaLaunchAttributeProgrammaticStreamSerialization;
    attrs[0].val.programmaticStreamSerializationAllowed = 1;

    cudaLaunchConfig_t cfg = {};
    cfg.gridDim  = dim3(SCAT_BLOCKS + FILL_BLOCKS);
    cfg.blockDim = dim3(256);
    cfg.dynamicSmemBytes = 0;
    cfg.stream = 0;
    cfg.attrs = attrs;
    cfg.numAttrs = 1;
    cudaLaunchKernelEx(&cfg, scatter, x_feats, out);

    cudaLaunchConfig_t cfg2 = cfg;
    cfg2.gridDim = dim3(7, 800);
    cudaLaunchKernelEx(&cfg2, transpose_out, out);
}

// round 16
// speedup vs baseline: 1.1858x; 1.1858x over previous
#include <cuda_runtime.h>
#include <cuda_bf16.h>
#include <cstdint>

#define BB   8
#define NCAM 6
#define DD   41
#define FHH  8
#define FWW  22
#define CC   64
#define NXY  200
#define PTS_PER_CAM (DD*FHH*FWW)          /* 7216 */
#define NPTS (BB*NCAM*PTS_PER_CAM)        /* 346368 */
#define GRID_CELLS (BB*NXY*NXY)           /* 320000 */
#define NCAMS (BB*NCAM)                   /* 48 */
#define SCAT_BLOCKS (NPTS*4/256)          /* 5412: 4 lanes per point (R14 sweet spot) */
#define FILL_BLOCKS 1250                  /* 1250*4096 float4 = whole out */

// Scratch: channel-last voxel grid [B,200,200,C]  (81.92 MB, static device alloc)
// INVARIANT: all-zero at the start of every kernel_launch call. Static init
// zeroes it; transpose_out re-zeroes every touched cell after reading it.
__device__ float g_scratch[(size_t)GRID_CELLS * CC];
// Per-cell touched flag. INVARIANT: all-zero at call start; scatter sets,
// transpose_out reads + clears.
__device__ unsigned g_count[GRID_CELLS];
// Per-camera fused params: inv(post_rots)[9], post_trans[3], combine[9], trans[3]
__device__ float g_cam[NCAMS][24];
// Param-ready flag. INVARIANT: 0 at call start; cam_setup sets (release),
// scatter spins (acquire loads), transpose_out resets.
__device__ unsigned g_ready;

// ---------------------------------------------------------------------------
// Reciprocal without div.rn.f64: f32 estimate + 2 double Newton steps
// (< 1 double ulp — invisible after the final cast to f32).
__device__ __forceinline__ double rcp_newton(double d) {
    double r = (double)__frcp_rn((float)d);
    double e = fma(-d, r, 1.0);  r = fma(r, e, r);
    e        = fma(-d, r, 1.0);  r = fma(r, e, r);
    return r;
}

// ---------------------------------------------------------------------------
// Camera setup: 96 threads, one 3x3 inverse each, no f64 divides.
// PDL trigger at ENTRY so scatter's blocks launch immediately. Params are
// published via g_ready (release) the moment they're computed (~1 us in) —
// consumers need NOT wait for this grid to fully drain (~9 us).
__global__ void cam_setup(const float* __restrict__ rots,
                          const float* __restrict__ trans,
                          const float* __restrict__ intrins,
                          const float* __restrict__ post_rots,
                          const float* __restrict__ post_trans) {
    cudaTriggerProgrammaticLaunchCompletion();
    __shared__ double sik[NCAMS][9];     // inv(intrins)
    int t = threadIdx.x;                 // 0..95
    int role = t / NCAMS;                // 0: post_rots, 1: intrins
    int cam  = t - role * NCAMS;

    if (t < 2 * NCAMS) {
        const float* src = (role == 0 ? post_rots : intrins) + cam * 9;
        double a[9];
        #pragma unroll
        for (int k = 0; k < 9; k++) a[k] = src[k];
        double det = a[0]*(a[4]*a[8] - a[5]*a[7])
                   + a[1]*(a[5]*a[6] - a[3]*a[8])
                   + a[2]*(a[3]*a[7] - a[4]*a[6]);
        double id = rcp_newton(det);
        #pragma unroll
        for (int r = 0; r < 3; r++) {
            #pragma unroll
            for (int c = 0; c < 3; c++) {
                int c1 = (c + 1) % 3, c2 = (c + 2) % 3;
                int r1 = (r + 1) % 3, r2 = (r + 2) % 3;
                double adj = a[c1*3 + r1] * a[c2*3 + r2]
                           - a[c1*3 + r2] * a[c2*3 + r1];
                double v = adj * id;
                if (role == 0) g_cam[cam][r*3 + c] = (float)v;
                else           sik[cam][r*3 + c]   = v;
            }
        }
        if (role == 0) {
            #pragma unroll
            for (int j = 0; j < 3; j++) {
                g_cam[cam][9 + j]  = post_trans[cam*3 + j];
                g_cam[cam][21 + j] = trans[cam*3 + j];
            }
        }
    }
    __syncthreads();
    if (t < NCAMS) {
        const float* rt = rots + t * 9;
        #pragma unroll
        for (int r = 0; r < 3; r++) {
            #pragma unroll
            for (int c = 0; c < 3; c++) {
                double s = (double)rt[r*3+0] * sik[t][0*3 + c]
                         + (double)rt[r*3+1] * sik[t][1*3 + c]
                         + (double)rt[r*3+2] * sik[t][2*3 + c];
                g_cam[t][12 + r*3 + c] = (float)s;
            }
        }
    }
    __syncthreads();
    __threadfence();
    if (t == 0) atomicExch(&g_ready, 1u);   // release-publish params
}

// ---------------------------------------------------------------------------
// Fused output-zero-fill + voxelize + scatter-add.
// Blocks [0, FILL_BLOCKS) zero d_out — no param dependency, never wait.
// Remaining blocks: FOUR lanes per point; thread 0 spin-waits on g_ready with
// acquire LOADS (L2 read path, no atomic-unit serialization), so the atomic
// phase starts as soon as params are WRITTEN, not when cam_setup's grid
// drains. Features loaded ONLY for points surviving the cull (~20%).
__global__ void scatter(const float* __restrict__ x_feats,
                        float* __restrict__ out) {
    int tid = threadIdx.x;               // 256 threads
    int bid = blockIdx.x;

    if (bid < FILL_BLOCKS) {
        float4* o4 = reinterpret_cast<float4*>(out);
        float4 z4 = make_float4(0.f, 0.f, 0.f, 0.f);
        int base = bid * 4096 + tid;
        #pragma unroll
        for (int i = 0; i < 16; i++)
            __stcs(o4 + base + i * 256, z4);
        return;
    }

    // Spin-acquire on the param flag (thread 0 only; others park at the bar).
    if (tid == 0) {
        unsigned v;
        asm volatile("ld.acquire.gpu.global.u32 %0, [%1];"
                     : "=r"(v) : "l"(&g_ready) : "memory");
        unsigned ns = 64;
        while (v == 0u) {
            __nanosleep(ns);
            if (ns < 2048) ns <<= 1;
            asm volatile("ld.acquire.gpu.global.u32 %0, [%1];"
                         : "=r"(v) : "l"(&g_ready) : "memory");
        }
    }
    __syncthreads();

    int gid = (bid - FILL_BLOCKS) * 256 + tid;   // exact grid, no guard
    int point = gid >> 2;
    int c4    = gid & 3;                 // which quarter of the 64 channels

    int cam = point / PTS_PER_CAM;
    int r   = point - cam * PTS_PER_CAM;
    int d   = r / (FHH * FWW);
    int r2  = r - d * (FHH * FWW);
    int h   = r2 / FWW;
    int w   = r2 - h * FWW;

    const float* cp = g_cam[cam];
    const float XSTEP = 351.0f / 21.0f;   // matches f32 linspace step
    const float YSTEP = 127.0f / 7.0f;
    float fx = (float)w * XSTEP;
    float fy = (float)h * YSTEP;
    float fz = 4.0f + (float)d;

    float px = fx - cp[9];
    float py = fy - cp[10];
    float pz = fz - cp[11];
    // q = inv(post_rots) @ p   (fma chain, k-order accumulation)
    float q0 = fmaf(cp[2], pz, fmaf(cp[1], py, cp[0]*px));
    float q1 = fmaf(cp[5], pz, fmaf(cp[4], py, cp[3]*px));
    float q2 = fmaf(cp[8], pz, fmaf(cp[7], py, cp[6]*px));
    // unproject: (u*d, v*d, d)
    float r0 = q0 * q2;
    float r1 = q1 * q2;
    float r2v = q2;
    // geom = combine @ r + trans
    float g0 = fmaf(cp[14], r2v, fmaf(cp[13], r1, cp[12]*r0)) + cp[21];
    float g1 = fmaf(cp[17], r2v, fmaf(cp[16], r1, cp[15]*r0)) + cp[22];
    float g2 = fmaf(cp[20], r2v, fmaf(cp[19], r1, cp[18]*r0)) + cp[23];

    // quantize: (geom - (BX - DX/2)) / DX, truncate toward zero
    float v0 = (g0 + 50.0f) / 0.5f;
    float v1 = (g1 + 50.0f) / 0.5f;
    float v2 = (g2 + 10.0f) / 20.0f;
    int i0 = (int)v0;
    int i1 = (int)v1;
    int i2 = (int)v2;

    if (i0 < 0 || i0 >= NXY || i1 < 0 || i1 >= NXY || i2 != 0) return;
    int b   = cam / NCAM;
    int vox = (b * NXY + i0) * NXY + i1;

    if (c4 == 0) g_count[vox] = 1u;   // benign race: all writers store 1

    // Features loaded only for kept points: 4 independent float4s.
    const float4* xf = reinterpret_cast<const float4*>(x_feats) + point * 16 + c4;
    float4 f0 = __ldcs(xf);
    float4 f1 = __ldcs(xf + 4);
    float4 f2 = __ldcs(xf + 8);
    float4 f3 = __ldcs(xf + 12);
    float* dst = g_scratch + (unsigned)vox * CC + c4 * 4;
    asm volatile("red.global.add.v4.f32 [%0], {%1,%2,%3,%4};"
                 :: "l"(dst), "f"(f0.x), "f"(f0.y), "f"(f0.z), "f"(f0.w) : "memory");
    asm volatile("red.global.add.v4.f32 [%0], {%1,%2,%3,%4};"
                 :: "l"(dst + 16), "f"(f1.x), "f"(f1.y), "f"(f1.z), "f"(f1.w) : "memory");
    asm volatile("red.global.add.v4.f32 [%0], {%1,%2,%3,%4};"
                 :: "l"(dst + 32), "f"(f2.x), "f"(f2.y), "f"(f2.z), "f"(f2.w) : "memory");
    asm volatile("red.global.add.v4.f32 [%0], {%1,%2,%3,%4};"
                 :: "l"(dst + 48), "f"(f3.x), "f"(f3.y), "f"(f3.z), "f"(f3.w) : "memory");
}

// ---------------------------------------------------------------------------
// Transpose [B,200(x),200(y),C] -> out [B,C,200(x),200(y)] — TOUCHED TILES
// ONLY. Untouched tiles were already zero-filled by scatter's fill blocks:
// skip read AND write. Touched cells are read once and zeroed behind the
// read (maintains the all-zero scratch invariant). g_count always cleared;
// g_ready reset here for the next replay.
__global__ void transpose_out(float* __restrict__ out) {
    __shared__ float tile[2][32][65];
    __shared__ unsigned s_touch[2];
    int tid = threadIdx.x;               // 256 threads
    int xg  = blockIdx.y;                // 0..799 -> 2 consecutive bx
    int y0  = blockIdx.x * 32;
    int bx0 = xg * 2;
    int b   = bx0 / NXY;                 // 200 % 2 == 0: never crosses b
    int x0  = bx0 - b * NXY;

    cudaGridDependencySynchronize();    // wait for scatter's atomics/flags

    if (blockIdx.x == 0 && blockIdx.y == 0 && tid == 0) g_ready = 0u;

    if (tid < 64) {
        int u  = tid >> 5;
        int yl = tid & 31;
        int y  = y0 + yl;
        unsigned fl = 0u;
        if (y < NXY) {
            int cell = (bx0 + u) * NXY + y;
            fl = g_count[cell];
            if (fl) g_count[cell] = 0u;
        }
        unsigned m = __ballot_sync(0xffffffffu, fl != 0u);
        if (yl == 0) s_touch[u] = m;
    }
    __syncthreads();

    if ((s_touch[0] | s_touch[1]) == 0u) return;   // fill already wrote zeros

    // Load phase: thread covers (c4, ylo) and (c4, ylo+16) for both rows.
    int c4  = tid & 15;
    int ylo = tid >> 4;                  // 0..15
    float4* sc4 = reinterpret_cast<float4*>(g_scratch);
    float4 z4 = make_float4(0.f, 0.f, 0.f, 0.f);
    #pragma unroll
    for (int u = 0; u < 2; u++) {
        unsigned m = s_touch[u];
        if (!m) continue;                // tile[u] stale; store phase skips it
        #pragma unroll
        for (int i = 0; i < 2; i++) {
            int yl = ylo + 16 * i;
            int yg = y0 + yl;
            bool live = (yg < NXY) && ((m >> yl) & 1u);
            float4 v = z4;
            unsigned idx = (unsigned)((bx0 + u) * NXY + yg) * 16 + c4;
            if (live) {
                v = __ldcs(sc4 + idx);
                __stcs(sc4 + idx, z4);
            }
            if (yg < NXY) {
                tile[u][yl][c4 * 4 + 0] = v.x;
                tile[u][yl][c4 * 4 + 1] = v.y;
                tile[u][yl][c4 * 4 + 2] = v.z;
                tile[u][yl][c4 * 4 + 3] = v.w;
            }
        }
    }
    __syncthreads();

    // Store phase: float4 along y, fully coalesced; conflict-free smem reads.
    int lane = tid & 31;
    int warp = tid >> 5;                 // 0..7
    int cgrp = lane >> 3;                // 0..3
    int yseg = lane & 7;                 // 0..7
    int yg4  = y0 + yseg * 4;
    float4* out4 = reinterpret_cast<float4*>(out);

    if (yg4 < NXY) {
        #pragma unroll
        for (int u = 0; u < 2; u++) {
            if (!s_touch[u]) continue;   // zeros already present from fill
            int x = x0 + u;
            #pragma unroll
            for (int j = 0; j < 2; j++) {
                int c = warp * 4 + cgrp + j * 32;
                int yl = yseg * 4;
                float4 v;
                v.x = tile[u][yl + 0][c];
                v.y = tile[u][yl + 1][c];
                v.z = tile[u][yl + 2][c];
                v.w = tile[u][yl + 3][c];
                unsigned o4 = ((((unsigned)b * CC + c) * NXY + x) * NXY + yg4) >> 2;
                __stcs(out4 + o4, v);
            }
        }
    }
}

// ---------------------------------------------------------------------------
extern "C" void kernel_launch(void* const* d_in, const int* in_sizes, int n_in,
                              void* d_out, int out_size) {
    const float* x_feats    = (const float*)d_in[0];
    const float* rots       = (const float*)d_in[1];
    const float* trans      = (const float*)d_in[2];
    const float* intrins    = (const float*)d_in[3];
    const float* post_rots  = (const float*)d_in[4];
    const float* post_trans = (const float*)d_in[5];
    float* out = (float*)d_out;

    cam_setup<<<1, 96>>>(rots, trans, intrins, post_rots, post_trans);

    cudaLaunchAttribute attrs[1];
    attrs[0].id = cudaLaunchAttributeProgrammaticStreamSerialization;
    attrs[0].val.programmaticStreamSerializationAllowed = 1;

    cudaLaunchConfig_t cfg = {};
    cfg.gridDim  = dim3(SCAT_BLOCKS + FILL_BLOCKS);
    cfg.blockDim = dim3(256);
    cfg.dynamicSmemBytes = 0;
    cfg.stream = 0;
    cfg.attrs = attrs;
    cfg.numAttrs = 1;
    cudaLaunchKernelEx(&cfg, scatter, x_feats, out);

    cudaLaunchConfig_t cfg2 = cfg;
    cfg2.gridDim = dim3(7, 800);
    cudaLaunchKernelEx(&cfg2, transpose_out, out);
}